// round 7
// baseline (speedup 1.0000x reference)
#include <cuda_runtime.h>
#include <math.h>

// EdgeDetection: gray -> gauss3x3(sigma=0.8) -> scharr x/y -> L2 mag, reflect-101.
// Separable composite 5-tap filters on gray. Accumulator formulation:
// each thread owns one float4 column strip x 2 output rows; walks 6 horizontal
// filter rows, accumulating sx/sy for both rows (no register ring).
// float4 LDG / LDS / STG throughout; streaming stores.

#define TW 128
#define TH 32
#define GH 36            // TH + 4 halo rows
#define GSTRIDE 136      // smem row stride in floats; interior cols [4,132)
#define NTHREADS 512

__device__ __forceinline__ int reflect101(int v, int n) {
    v = (v < 0) ? -v : v;
    v = (v >= n) ? (2 * n - 2 - v) : v;
    return v;
}

__global__ __launch_bounds__(NTHREADS, 3)
void edge_detect_kernel(const float* __restrict__ x, float* __restrict__ out,
                        int H, int W) {
    __shared__ float g[GH][GSTRIDE];

    const int x0 = blockIdx.x * TW;
    const int y0 = blockIdx.y * TH;
    const int b  = blockIdx.z;
    const int tid = threadIdx.x;

    // 1-D Gaussian [ga, gb, ga] for k=3 sigma=0.8
    const float e  = expf(-0.78125f);
    const float s  = 1.0f / (2.0f * e + 1.0f);
    const float ga = e * s;
    const float gb = s;
    // Smooth5 = conv([ga,gb,ga],[3,10,3]); Deriv5 = conv([ga,gb,ga],[-1,0,1])
    const float w0 = 3.0f * ga;
    const float w1 = 10.0f * ga + 3.0f * gb;
    const float w2 = 6.0f * ga + 10.0f * gb;

    const size_t plane = (size_t)H * W;
    const float* Rp = x + (size_t)b * 3 * plane;
    const float* Gp = Rp + plane;
    const float* Bp = Gp + plane;

    // ---- Stage 1a: interior gray, float4 loads. 36 rows x 32 strips = 1152 ----
    #pragma unroll 3
    for (int idx = tid; idx < GH * (TW / 4); idx += NTHREADS) {
        const int i  = idx >> 5;          // gray row 0..35
        const int jv = idx & 31;          // float4 strip 0..31
        const int gy = reflect101(y0 + i - 2, H);
        const size_t o = (size_t)gy * W + x0 + 4 * jv;
        const float4 r4 = __ldg((const float4*)(Rp + o));
        const float4 g4 = __ldg((const float4*)(Gp + o));
        const float4 b4 = __ldg((const float4*)(Bp + o));
        float4 gr;
        gr.x = 0.299f * r4.x + 0.587f * g4.x + 0.114f * b4.x;
        gr.y = 0.299f * r4.y + 0.587f * g4.y + 0.114f * b4.y;
        gr.z = 0.299f * r4.z + 0.587f * g4.z + 0.114f * b4.z;
        gr.w = 0.299f * r4.w + 0.587f * g4.w + 0.114f * b4.w;
        *(float4*)&g[i][4 + 4 * jv] = gr;
    }
    // ---- Stage 1b: halo columns (smem cols 2,3,132,133), scalar ----
    if (tid < GH * 4) {
        const int i  = tid >> 2;
        const int hc = tid & 3;
        const int sj = (hc < 2) ? (2 + hc) : (130 + hc);
        const int gxr = (hc < 2) ? (x0 - 2 + hc) : (x0 + 126 + hc);
        const int gx = reflect101(gxr, W);
        const int gy = reflect101(y0 + i - 2, H);
        const size_t o = (size_t)gy * W + gx;
        g[i][sj] = 0.299f * __ldg(Rp + o) + 0.587f * __ldg(Gp + o) + 0.114f * __ldg(Bp + o);
    }
    __syncthreads();

    // ---- Stage 2+3: 6 horizontal rows -> accumulate 2 output rows ----
    const int c  = tid & 31;      // float4 strip (output cols 4c..4c+3)
    const int rp = tid >> 5;      // row pair 0..15
    const int r0 = 2 * rp;        // first local output row

#define HROW(k, HX, HY) do {                                               \
        const float4 A  = *(const float4*)&g[k][4 * c];                    \
        const float4 Bv = *(const float4*)&g[k][4 * c + 4];                \
        const float4 Cv = *(const float4*)&g[k][4 * c + 8];                \
        HX.x = ga * (Bv.z - A.z)  + gb * (Bv.y - A.w);                     \
        HX.y = ga * (Bv.w - A.w)  + gb * (Bv.z - Bv.x);                    \
        HX.z = ga * (Cv.x - Bv.x) + gb * (Bv.w - Bv.y);                    \
        HX.w = ga * (Cv.y - Bv.y) + gb * (Cv.x - Bv.z);                    \
        HY.x = w0 * (A.z + Bv.z)  + w1 * (A.w + Bv.y)  + w2 * Bv.x;        \
        HY.y = w0 * (A.w + Bv.w)  + w1 * (Bv.x + Bv.z) + w2 * Bv.y;        \
        HY.z = w0 * (Bv.x + Cv.x) + w1 * (Bv.y + Bv.w) + w2 * Bv.z;        \
        HY.w = w0 * (Bv.y + Cv.y) + w1 * (Bv.z + Cv.x) + w2 * Bv.w;        \
    } while (0)

#define ACC4(ACC, W_, V) do { ACC.x += (W_) * V.x; ACC.y += (W_) * V.y;    \
                              ACC.z += (W_) * V.z; ACC.w += (W_) * V.w; } while (0)

    float4 sx0 = {0,0,0,0}, sy0 = {0,0,0,0};
    float4 sx1 = {0,0,0,0}, sy1 = {0,0,0,0};
    float4 HX, HY;

    // output row r taps gray rows r..r+4 (smem indices); row pair shares 4 rows
    HROW(r0 + 0, HX, HY);
    ACC4(sx0, w0, HX); ACC4(sy0, -ga, HY);
    HROW(r0 + 1, HX, HY);
    ACC4(sx0, w1, HX); ACC4(sy0, -gb, HY); ACC4(sx1, w0, HX); ACC4(sy1, -ga, HY);
    HROW(r0 + 2, HX, HY);
    ACC4(sx0, w2, HX);                     ACC4(sx1, w1, HX); ACC4(sy1, -gb, HY);
    HROW(r0 + 3, HX, HY);
    ACC4(sx0, w1, HX); ACC4(sy0,  gb, HY); ACC4(sx1, w2, HX);
    HROW(r0 + 4, HX, HY);
    ACC4(sx0, w0, HX); ACC4(sy0,  ga, HY); ACC4(sx1, w1, HX); ACC4(sy1,  gb, HY);
    HROW(r0 + 5, HX, HY);
                                           ACC4(sx1, w0, HX); ACC4(sy1,  ga, HY);

    float4 m0, m1;
    m0.x = sqrtf(sx0.x * sx0.x + sy0.x * sy0.x);
    m0.y = sqrtf(sx0.y * sx0.y + sy0.y * sy0.y);
    m0.z = sqrtf(sx0.z * sx0.z + sy0.z * sy0.z);
    m0.w = sqrtf(sx0.w * sx0.w + sy0.w * sy0.w);
    m1.x = sqrtf(sx1.x * sx1.x + sy1.x * sy1.x);
    m1.y = sqrtf(sx1.y * sx1.y + sy1.y * sy1.y);
    m1.z = sqrtf(sx1.z * sx1.z + sy1.z * sy1.z);
    m1.w = sqrtf(sx1.w * sx1.w + sy1.w * sy1.w);

    float* outp = out + (size_t)b * 3 * plane + (size_t)(y0 + r0) * W + (x0 + 4 * c);
    __stcs((float4*)(outp),                 m0);
    __stcs((float4*)(outp + plane),         m0);
    __stcs((float4*)(outp + 2 * plane),     m0);
    __stcs((float4*)(outp + W),             m1);
    __stcs((float4*)(outp + W + plane),     m1);
    __stcs((float4*)(outp + W + 2 * plane), m1);

#undef HROW
#undef ACC4
}

extern "C" void kernel_launch(void* const* d_in, const int* in_sizes, int n_in,
                              void* d_out, int out_size) {
    const float* x = (const float*)d_in[0];
    float* out = (float*)d_out;
    const int B = 8, H = 1024, W = 1024;

    dim3 grid(W / TW, H / TH, B);
    edge_detect_kernel<<<grid, NTHREADS>>>(x, out, H, W);
}

// round 8
// speedup vs baseline: 1.0726x; 1.0726x over previous
#include <cuda_runtime.h>
#include <math.h>

// EdgeDetection: gray -> gauss3x3(sigma=0.8) -> scharr x/y -> L2 mag, reflect-101.
// Separable composite 5-tap filters on gray. FULLY STREAMING: no smem, no
// __syncthreads. Each warp owns a 128-col strip (float4 quad per lane) and
// walks rows with a 5-deep register ring; horizontal taps via warp shuffles,
// lane 0/31 patch halo columns with scalar loads. float4 LDG/STG throughout.

#define RPT 16            // output rows per warp
#define WARPS_PER_BLOCK 4
#define NTHREADS (32 * WARPS_PER_BLOCK)

__device__ __forceinline__ int reflect101(int v, int n) {
    v = (v < 0) ? -v : v;
    v = (v >= n) ? (2 * n - 2 - v) : v;
    return v;
}

__global__ __launch_bounds__(NTHREADS)
void edge_detect_kernel(const float* __restrict__ x, float* __restrict__ out,
                        int H, int W) {
    const int lane = threadIdx.x & 31;
    const int wrp  = threadIdx.x >> 5;
    const int x0   = blockIdx.x * 128;                 // strip start col
    const int r0   = (blockIdx.y * WARPS_PER_BLOCK + wrp) * RPT; // first output row
    const int b    = blockIdx.z;
    const int gx   = x0 + lane * 4;                    // this lane's quad start col

    // 1-D Gaussian [ga, gb, ga] for k=3 sigma=0.8
    const float e  = expf(-0.78125f);
    const float s  = 1.0f / (2.0f * e + 1.0f);
    const float ga = e * s;
    const float gb = s;
    // Smooth5 = conv([ga,gb,ga],[3,10,3]); Deriv5 = conv([ga,gb,ga],[-1,0,1])
    const float w0 = 3.0f * ga;
    const float w1 = 10.0f * ga + 3.0f * gb;
    const float w2 = 6.0f * ga + 10.0f * gb;

    const size_t plane = (size_t)H * W;
    const float* Rp = x + (size_t)b * 3 * plane;
    const float* Gp = Rp + plane;
    const float* Bp = Gp + plane;

    // Column halo indices (row-independent; reflect only matters at image edge)
    const int xm2 = reflect101(x0 - 2, W);
    const int xm1 = reflect101(x0 - 1, W);
    const int xp4 = reflect101(x0 + 128, W);
    const int xp5 = reflect101(x0 + 129, W);

#define GRAY1(ry, c) (0.299f * __ldg(Rp + (size_t)(ry) * W + (c)) \
                    + 0.587f * __ldg(Gp + (size_t)(ry) * W + (c)) \
                    + 0.114f * __ldg(Bp + (size_t)(ry) * W + (c)))

    // Load gray row k (relative), compute horizontal deriv/smooth 5-taps.
#define HROWK(k, HX, HY) do {                                              \
        const int ry = reflect101(r0 - 2 + (k), H);                        \
        const size_t o = (size_t)ry * W + gx;                              \
        const float4 r4 = __ldg((const float4*)(Rp + o));                  \
        const float4 g4 = __ldg((const float4*)(Gp + o));                  \
        const float4 b4 = __ldg((const float4*)(Bp + o));                  \
        float4 q;                                                          \
        q.x = 0.299f * r4.x + 0.587f * g4.x + 0.114f * b4.x;               \
        q.y = 0.299f * r4.y + 0.587f * g4.y + 0.114f * b4.y;               \
        q.z = 0.299f * r4.z + 0.587f * g4.z + 0.114f * b4.z;               \
        q.w = 0.299f * r4.w + 0.587f * g4.w + 0.114f * b4.w;               \
        float Lm2 = __shfl_up_sync(0xffffffffu, q.z, 1);                   \
        float Lm1 = __shfl_up_sync(0xffffffffu, q.w, 1);                   \
        float Rq4 = __shfl_down_sync(0xffffffffu, q.x, 1);                 \
        float Rq5 = __shfl_down_sync(0xffffffffu, q.y, 1);                 \
        if (lane == 0)  { Lm2 = GRAY1(ry, xm2); Lm1 = GRAY1(ry, xm1); }    \
        if (lane == 31) { Rq4 = GRAY1(ry, xp4); Rq5 = GRAY1(ry, xp5); }    \
        HX.x = ga * (q.z - Lm2) + gb * (q.y - Lm1);                        \
        HX.y = ga * (q.w - Lm1) + gb * (q.z - q.x);                        \
        HX.z = ga * (Rq4 - q.x) + gb * (q.w - q.y);                        \
        HX.w = ga * (Rq5 - q.y) + gb * (Rq4 - q.z);                        \
        HY.x = w0 * (Lm2 + q.z) + w1 * (Lm1 + q.y) + w2 * q.x;             \
        HY.y = w0 * (Lm1 + q.w) + w1 * (q.x + q.z) + w2 * q.y;             \
        HY.z = w0 * (q.x + Rq4) + w1 * (q.y + q.w) + w2 * q.z;             \
        HY.w = w0 * (q.y + Rq5) + w1 * (q.z + Rq4) + w2 * q.w;             \
    } while (0)

    float4 hx0, hx1, hx2, hx3, hx4;
    float4 hy0, hy1, hy2, hy3, hy4;
    HROWK(0, hx0, hy0);
    HROWK(1, hx1, hy1);
    HROWK(2, hx2, hy2);
    HROWK(3, hx3, hy3);

    float* outp = out + (size_t)b * 3 * plane + (size_t)r0 * W + gx;

    #pragma unroll 4
    for (int t = 0; t < RPT; t++) {
        HROWK(t + 4, hx4, hy4);
        float4 m;
        {
            const float sx = w0 * (hx0.x + hx4.x) + w1 * (hx1.x + hx3.x) + w2 * hx2.x;
            const float sy = ga * (hy4.x - hy0.x) + gb * (hy3.x - hy1.x);
            m.x = sqrtf(sx * sx + sy * sy);
        }
        {
            const float sx = w0 * (hx0.y + hx4.y) + w1 * (hx1.y + hx3.y) + w2 * hx2.y;
            const float sy = ga * (hy4.y - hy0.y) + gb * (hy3.y - hy1.y);
            m.y = sqrtf(sx * sx + sy * sy);
        }
        {
            const float sx = w0 * (hx0.z + hx4.z) + w1 * (hx1.z + hx3.z) + w2 * hx2.z;
            const float sy = ga * (hy4.z - hy0.z) + gb * (hy3.z - hy1.z);
            m.z = sqrtf(sx * sx + sy * sy);
        }
        {
            const float sx = w0 * (hx0.w + hx4.w) + w1 * (hx1.w + hx3.w) + w2 * hx2.w;
            const float sy = ga * (hy4.w - hy0.w) + gb * (hy3.w - hy1.w);
            m.w = sqrtf(sx * sx + sy * sy);
        }
        *(float4*)(outp)             = m;
        *(float4*)(outp + plane)     = m;
        *(float4*)(outp + 2 * plane) = m;
        outp += W;
        hx0 = hx1; hx1 = hx2; hx2 = hx3; hx3 = hx4;
        hy0 = hy1; hy1 = hy2; hy2 = hy3; hy3 = hy4;
    }
#undef HROWK
#undef GRAY1
}

extern "C" void kernel_launch(void* const* d_in, const int* in_sizes, int n_in,
                              void* d_out, int out_size) {
    const float* x = (const float*)d_in[0];
    float* out = (float*)d_out;
    const int B = 8, H = 1024, W = 1024;

    // 8 col-strips x (1024 / (4 warps * 16 rows)) x batch
    dim3 grid(W / 128, H / (WARPS_PER_BLOCK * RPT), B);
    edge_detect_kernel<<<grid, NTHREADS>>>(x, out, H, W);
}

// round 10
// speedup vs baseline: 1.1869x; 1.1066x over previous
#include <cuda_runtime.h>
#include <math.h>
#include <stdint.h>

// EdgeDetection: gray -> gauss3x3(sigma=0.8) -> scharr x/y -> L2 mag, reflect-101.
// R2 structure (best: 36.9us kernel) + cache policy only:
//   - input loads:  createpolicy L2::evict_last + ld.global.nc.L2::cache_hint
//   - output stores: st.global.cs (evict-first)

#define TW 64
#define TH 64
#define GW 68           // TW + 4 halo
#define GH 68           // TH + 4 halo
#define NTHREADS 256
#define ROWS_PER_THREAD 16   // TH / (NTHREADS / TW)

__device__ __forceinline__ int reflect101(int v, int n) {
    v = (v < 0) ? -v : v;
    v = (v >= n) ? (2 * n - 2 - v) : v;
    return v;
}

__device__ __forceinline__ uint64_t mk_evict_last_policy() {
    uint64_t pol;
    asm("createpolicy.fractional.L2::evict_last.b64 %0, 1.0;" : "=l"(pol));
    return pol;
}

__device__ __forceinline__ float ldg_pol(const float* p, uint64_t pol) {
    float v;
    asm volatile("ld.global.nc.L2::cache_hint.f32 %0, [%1], %2;"
                 : "=f"(v) : "l"(p), "l"(pol));
    return v;
}

__global__ __launch_bounds__(NTHREADS)
void edge_detect_kernel(const float* __restrict__ x, float* __restrict__ out,
                        int H, int W) {
    __shared__ float g[GH][GW];

    const int x0 = blockIdx.x * TW;
    const int y0 = blockIdx.y * TH;
    const int b  = blockIdx.z;
    const int tid = threadIdx.x;

    const uint64_t pol = mk_evict_last_policy();

    // 1-D Gaussian [ga, gb, ga] for k=3 sigma=0.8
    const float e  = expf(-0.78125f);
    const float s  = 1.0f / (2.0f * e + 1.0f);
    const float ga = e * s;
    const float gb = s;
    // Smooth5 = conv([ga,gb,ga],[3,10,3]); Deriv5 = conv([ga,gb,ga],[-1,0,1])
    const float w0 = 3.0f * ga;
    const float w1 = 10.0f * ga + 3.0f * gb;
    const float w2 = 6.0f * ga + 10.0f * gb;

    const size_t plane = (size_t)H * W;
    const float* Rp = x + (size_t)b * 3 * plane;
    const float* Gp = Rp + plane;
    const float* Bp = Gp + plane;

    // ---- Stage 1: grayscale into smem with reflect-101 halo of 2 ----
    #pragma unroll 5
    for (int idx = tid; idx < GH * GW; idx += NTHREADS) {
        const int i = idx / GW;
        const int j = idx - i * GW;
        const int gy = reflect101(y0 + i - 2, H);
        const int gx = reflect101(x0 + j - 2, W);
        const size_t o = (size_t)gy * W + gx;
        g[i][j] = 0.299f * ldg_pol(Rp + o, pol)
                + 0.587f * ldg_pol(Gp + o, pol)
                + 0.114f * ldg_pol(Bp + o, pol);
    }
    __syncthreads();

    // ---- Stage 2+3: horizontal 5-tap + vertical 5-tap via register ring ----
    const int c  = tid & (TW - 1);          // output column within tile, 0..63
    const int rg = tid >> 6;                // row group 0..3
    const int rbase = rg * ROWS_PER_THREAD; // first local output row

#define HROW(k, HX, HY) do {                                              \
        const float g0 = g[k][c],     g1 = g[k][c + 1], g2 = g[k][c + 2], \
                    g3 = g[k][c + 3], g4 = g[k][c + 4];                   \
        HX = ga * (g4 - g0) + gb * (g3 - g1);                             \
        HY = w0 * (g0 + g4) + w1 * (g1 + g3) + w2 * g2;                   \
    } while (0)

    float hx0, hx1, hx2, hx3, hx4;
    float hy0, hy1, hy2, hy3, hy4;
    HROW(rbase + 0, hx0, hy0);
    HROW(rbase + 1, hx1, hy1);
    HROW(rbase + 2, hx2, hy2);
    HROW(rbase + 3, hx3, hy3);

    float* outp = out + (size_t)b * 3 * plane + (size_t)(y0 + rbase) * W + (x0 + c);

    #pragma unroll
    for (int t = 0; t < ROWS_PER_THREAD; t++) {
        HROW(rbase + t + 4, hx4, hy4);
        const float sx = w0 * (hx0 + hx4) + w1 * (hx1 + hx3) + w2 * hx2;
        const float sy = ga * (hy4 - hy0) + gb * (hy3 - hy1);
        const float mag = sqrtf(sx * sx + sy * sy);
        __stcs(outp, mag);
        __stcs(outp + plane, mag);
        __stcs(outp + 2 * plane, mag);
        outp += W;
        hx0 = hx1; hx1 = hx2; hx2 = hx3; hx3 = hx4;
        hy0 = hy1; hy1 = hy2; hy2 = hy3; hy3 = hy4;
    }
#undef HROW
}

extern "C" void kernel_launch(void* const* d_in, const int* in_sizes, int n_in,
                              void* d_out, int out_size) {
    const float* x = (const float*)d_in[0];
    float* out = (float*)d_out;
    const int B = 8, H = 1024, W = 1024;

    dim3 grid(W / TW, H / TH, B);
    edge_detect_kernel<<<grid, NTHREADS>>>(x, out, H, W);
}